// round 8
// baseline (speedup 1.0000x reference)
#include <cuda_runtime.h>
#include <cuda_bf16.h>
#include <math.h>

#define F 128
#define NMAX 50000
#define EMAX 800000
#define CAP 64      // bucket capacity per destination row (P(deg>=64) ~ 1e-13)
#define MT 64       // rows per epilogue tile

// static scratch (no allocations allowed)
__device__ float  g_S[(size_t)NMAX * F];           // S = (1-a)*A@x + a*h0
__device__ float2 g_slots[(size_t)NMAX * CAP];     // (src_bits, w) buckets
__device__ int    g_cnt[NMAX];
__device__ float4 g_over[EMAX];                    // overflow edges (src,dst,w,-)
__device__ int    g_overcnt;

// ---------------------------------------------------------------------------
// Kernel 1: zero bucket counters + overflow counter
// ---------------------------------------------------------------------------
__global__ void zero_cnt_kernel(int Nn) {
    int i = blockIdx.x * blockDim.x + threadIdx.x;
    if (i < Nn) g_cnt[i] = 0;
    if (i == 0) g_overcnt = 0;
}

// ---------------------------------------------------------------------------
// Kernel 2: bucket fill. One thread per edge (R3-proven version).
// ---------------------------------------------------------------------------
__global__ void fill_kernel(const float* __restrict__ edge_w,
                            const int* __restrict__ edge_src,
                            const int* __restrict__ edge_dst,
                            int E) {
    int e = blockIdx.x * blockDim.x + threadIdx.x;
    if (e >= E) return;
    int d = edge_dst[e];
    int s = edge_src[e];
    float w = edge_w[e];
    int pos = atomicAdd(&g_cnt[d], 1);
    if (pos < CAP) {
        g_slots[(size_t)d * CAP + pos] = make_float2(__int_as_float(s), w);
    } else {
        int o = atomicAdd(&g_overcnt, 1);
        if (o < EMAX)
            g_over[o] = make_float4(__int_as_float(s), __int_as_float(d), w, 0.f);
    }
}

// ---------------------------------------------------------------------------
// Kernel 3: gather + S fuse. One warp per row (identical to R7, passed).
// ---------------------------------------------------------------------------
__global__ void gather_kernel(const float* __restrict__ x,
                              const float* __restrict__ h0,
                              const float* __restrict__ alpha_p,
                              int Nn) {
    int gtid = blockIdx.x * blockDim.x + threadIdx.x;
    int row = gtid >> 5;
    int lane = gtid & 31;
    if (row >= Nn) return;

    float alpha = alpha_p[0];
    float oma = 1.0f - alpha;

    int cnt_raw = g_cnt[row];
    int cnt = min(cnt_raw, CAP);

    float4 acc = make_float4(0.f, 0.f, 0.f, 0.f);
    const float2* slotp = g_slots + (size_t)row * CAP;

    for (int base = 0; base < cnt; base += 32) {
        int m = min(32, cnt - base);
        float2 myslot = (lane < m) ? slotp[base + lane] : make_float2(0.f, 0.f);
        int ms = __float_as_int(myslot.x);
        #pragma unroll 4
        for (int e = 0; e < m; e++) {
            int   s  = __shfl_sync(0xffffffffu, ms, e);
            float wt = __shfl_sync(0xffffffffu, myslot.y, e);
            float4 v = ((const float4*)(x + (size_t)s * F))[lane];
            acc.x += wt * v.x;
            acc.y += wt * v.y;
            acc.z += wt * v.z;
            acc.w += wt * v.w;
        }
    }

    // overflow drain (statistically never; correct for any degree dist)
    if (cnt_raw > CAP) {
        int oc = g_overcnt;
        if (oc > EMAX) oc = EMAX;
        for (int o = 0; o < oc; o++) {
            float4 ov = g_over[o];                 // broadcast load
            if (__float_as_int(ov.y) == row) {
                int s = __float_as_int(ov.x);
                float wt = ov.z;
                float4 v = ((const float4*)(x + (size_t)s * F))[lane];
                acc.x += wt * v.x;
                acc.y += wt * v.y;
                acc.z += wt * v.z;
                acc.w += wt * v.w;
            }
        }
    }

    float4 hv = ((const float4*)(h0 + (size_t)row * F))[lane];
    float4 S;
    S.x = oma * acc.x + alpha * hv.x;
    S.y = oma * acc.y + alpha * hv.y;
    S.z = oma * acc.z + alpha * hv.z;
    S.w = oma * acc.w + alpha * hv.w;
    ((float4*)(g_S + (size_t)row * F))[lane] = S;
}

// ---------------------------------------------------------------------------
// Kernel 4: GEMM epilogue, smem holds ONLY W' (64 KB -> 3 blocks/SM, 24 warps).
//   out = S @ W' + x,  W' = theta*W + (1-theta)*I
// Warp owns 8 rows; S is read straight from g_S with uniform LDG.128
// (L2-resident, broadcast across the warp). FFMA2 column-pair packing:
// w-pairs come free from LDS.128 of Wp. 16 independent accumulators/thread.
// No per-tile syncthreads (no shared S staging).
// ---------------------------------------------------------------------------
#define PACK2(dst, lo, hi) \
    asm("mov.b64 %0, {%1, %2};" : "=l"(dst) : "f"(lo), "f"(hi))
#define UNPACK2(lo, hi, src) \
    asm("mov.b64 {%0, %1}, %2;" : "=f"(lo), "=f"(hi) : "l"(src))
#define FMA2(acc, a, b) \
    asm("fma.rn.f32x2 %0, %1, %2, %0;" : "+l"(acc) : "l"(a), "l"(b))

__global__ void __launch_bounds__(256, 3)
epilogue_kernel(const float* __restrict__ x,
                const float* __restrict__ weight,
                const float* __restrict__ lamda_p,
                const int* __restrict__ l_p,
                float* __restrict__ out,
                int Nn) {
    extern __shared__ float sh[];
    float* Wp = sh;            // 128x128 = 64 KB (only smem use)

    int tid = threadIdx.x;
    int cg = tid & 31;         // column group: cols 4cg .. 4cg+3
    int wrp = tid >> 5;        // warp id: rows 8*wrp .. 8*wrp+7 of the tile

    float theta = logf(lamda_p[0] / (float)l_p[0] + 1.0f);
    float omt = 1.0f - theta;

    // W'[k][j] = theta*W[k][j] + (k==j ? 1-theta : 0)
    for (int i = tid; i < F * F; i += 256) {
        int k = i >> 7;
        int j = i & 127;
        float v = theta * weight[i];
        if (k == j) v += omt;
        Wp[i] = v;
    }
    __syncthreads();

    int ntiles = (Nn + MT - 1) / MT;
    for (int t = blockIdx.x; t < ntiles; t += gridDim.x) {
        int rowbase = t * MT + wrp * 8;

        // per-row S pointers (clamp invalid rows to row 0; stores are guarded)
        const float4* srow[8];
        #pragma unroll
        for (int r = 0; r < 8; r++) {
            int row = rowbase + r;
            srow[r] = (const float4*)(g_S + (size_t)(row < Nn ? row : 0) * F);
        }

        unsigned long long acc[8][2];
        #pragma unroll
        for (int r = 0; r < 8; r++) { acc[r][0] = 0ull; acc[r][1] = 0ull; }

        #pragma unroll 2
        for (int k = 0; k < F; k += 4) {
            float4 w0 = *(const float4*)&Wp[(k + 0) * F + 4 * cg];
            float4 w1 = *(const float4*)&Wp[(k + 1) * F + 4 * cg];
            float4 w2 = *(const float4*)&Wp[(k + 2) * F + 4 * cg];
            float4 w3 = *(const float4*)&Wp[(k + 3) * F + 4 * cg];
            unsigned long long wp00, wp01, wp10, wp11,
                               wp20, wp21, wp30, wp31;
            PACK2(wp00, w0.x, w0.y); PACK2(wp01, w0.z, w0.w);
            PACK2(wp10, w1.x, w1.y); PACK2(wp11, w1.z, w1.w);
            PACK2(wp20, w2.x, w2.y); PACK2(wp21, w2.z, w2.w);
            PACK2(wp30, w3.x, w3.y); PACK2(wp31, w3.z, w3.w);
            #pragma unroll
            for (int r = 0; r < 8; r++) {
                float4 s4 = srow[r][k >> 2];       // uniform LDG.128 (L2)
                unsigned long long sp;
                PACK2(sp, s4.x, s4.x);
                FMA2(acc[r][0], sp, wp00);
                FMA2(acc[r][1], sp, wp01);
                PACK2(sp, s4.y, s4.y);
                FMA2(acc[r][0], sp, wp10);
                FMA2(acc[r][1], sp, wp11);
                PACK2(sp, s4.z, s4.z);
                FMA2(acc[r][0], sp, wp20);
                FMA2(acc[r][1], sp, wp21);
                PACK2(sp, s4.w, s4.w);
                FMA2(acc[r][0], sp, wp30);
                FMA2(acc[r][1], sp, wp31);
            }
        }

        #pragma unroll
        for (int r = 0; r < 8; r++) {
            int row = rowbase + r;
            if (row < Nn) {
                float a0, a1, a2, a3;
                UNPACK2(a0, a1, acc[r][0]);
                UNPACK2(a2, a3, acc[r][1]);
                size_t base = (size_t)row * F + 4 * cg;
                float4 xv = *(const float4*)(x + base);
                float4 o = make_float4(a0 + xv.x, a1 + xv.y, a2 + xv.z, a3 + xv.w);
                *(float4*)(out + base) = o;
            }
        }
    }
}

// ---------------------------------------------------------------------------
extern "C" void kernel_launch(void* const* d_in, const int* in_sizes, int n_in,
                              void* d_out, int out_size) {
    const float* x      = (const float*)d_in[0];
    const float* h0     = (const float*)d_in[1];
    const float* ew     = (const float*)d_in[2];
    const float* weight = (const float*)d_in[3];
    const float* lamda  = (const float*)d_in[4];
    const float* alpha  = (const float*)d_in[5];
    const int*   esrc   = (const int*)d_in[6];
    const int*   edst   = (const int*)d_in[7];
    const int*   lp     = (const int*)d_in[8];

    int Nn = in_sizes[0] / F;
    int E  = in_sizes[2];
    float* out = (float*)d_out;

    // 1) zero counters
    zero_cnt_kernel<<<(Nn + 255) / 256, 256>>>(Nn);

    // 2) bucket fill (one edge per thread)
    fill_kernel<<<(E + 255) / 256, 256>>>(ew, esrc, edst, E);

    // 3) gather + S fuse (one warp per row; inline overflow drain)
    long long gthreads = (long long)Nn * 32;
    gather_kernel<<<(int)((gthreads + 255) / 256), 256>>>(x, h0, alpha, Nn);

    // 4) GEMM epilogue (Wp-only smem -> 3 blocks/SM)
    int smem_bytes = F * F * (int)sizeof(float);   // 65536
    cudaFuncSetAttribute(epilogue_kernel,
                         cudaFuncAttributeMaxDynamicSharedMemorySize, smem_bytes);
    epilogue_kernel<<<444, 256, smem_bytes>>>(x, weight, lamda, lp, out, Nn);
}

// round 10
// speedup vs baseline: 1.2510x; 1.2510x over previous
#include <cuda_runtime.h>
#include <cuda_bf16.h>
#include <math.h>

#define F 128
#define NMAX 50000
#define EMAX 800000
#define CAP 64      // bucket capacity per destination row (P(deg>=64) ~ 1e-13)

typedef unsigned int   u32;
typedef unsigned short u16;

// static scratch (no allocations allowed)
__device__ float  g_S[(size_t)NMAX * F];           // S = (1-a)*A@x + a*h0
__device__ float2 g_slots[(size_t)NMAX * CAP];     // (src_bits, w) buckets
__device__ int    g_cnt[NMAX];
__device__ float4 g_over[EMAX];                    // overflow edges
__device__ int    g_overcnt;

// ---------------------------------------------------------------------------
// Kernel 1: zero bucket counters + overflow counter
// ---------------------------------------------------------------------------
__global__ void zero_cnt_kernel(int Nn) {
    int i = blockIdx.x * blockDim.x + threadIdx.x;
    if (i < Nn) g_cnt[i] = 0;
    if (i == 0) g_overcnt = 0;
}

// ---------------------------------------------------------------------------
// Kernel 2: bucket fill. One thread per edge (R3/R8-proven).
// ---------------------------------------------------------------------------
__global__ void fill_kernel(const float* __restrict__ edge_w,
                            const int* __restrict__ edge_src,
                            const int* __restrict__ edge_dst,
                            int E) {
    int e = blockIdx.x * blockDim.x + threadIdx.x;
    if (e >= E) return;
    int d = edge_dst[e];
    int s = edge_src[e];
    float w = edge_w[e];
    int pos = atomicAdd(&g_cnt[d], 1);
    if (pos < CAP) {
        g_slots[(size_t)d * CAP + pos] = make_float2(__int_as_float(s), w);
    } else {
        int o = atomicAdd(&g_overcnt, 1);
        if (o < EMAX)
            g_over[o] = make_float4(__int_as_float(s), __int_as_float(d), w, 0.f);
    }
}

// ---------------------------------------------------------------------------
// Kernel 3: gather + S fuse. One warp per row (R8-proven, inline overflow).
// ---------------------------------------------------------------------------
__global__ void gather_kernel(const float* __restrict__ x,
                              const float* __restrict__ h0,
                              const float* __restrict__ alpha_p,
                              int Nn) {
    int gtid = blockIdx.x * blockDim.x + threadIdx.x;
    int row = gtid >> 5;
    int lane = gtid & 31;
    if (row >= Nn) return;

    float alpha = alpha_p[0];
    float oma = 1.0f - alpha;

    int cnt_raw = g_cnt[row];
    int cnt = min(cnt_raw, CAP);

    float4 acc = make_float4(0.f, 0.f, 0.f, 0.f);
    const float2* slotp = g_slots + (size_t)row * CAP;

    for (int base = 0; base < cnt; base += 32) {
        int m = min(32, cnt - base);
        float2 myslot = (lane < m) ? slotp[base + lane] : make_float2(0.f, 0.f);
        int ms = __float_as_int(myslot.x);
        #pragma unroll 4
        for (int e = 0; e < m; e++) {
            int   s  = __shfl_sync(0xffffffffu, ms, e);
            float wt = __shfl_sync(0xffffffffu, myslot.y, e);
            float4 v = ((const float4*)(x + (size_t)s * F))[lane];
            acc.x += wt * v.x;
            acc.y += wt * v.y;
            acc.z += wt * v.z;
            acc.w += wt * v.w;
        }
    }

    if (cnt_raw > CAP) {                       // statistically never
        int oc = g_overcnt;
        if (oc > EMAX) oc = EMAX;
        for (int o = 0; o < oc; o++) {
            float4 ov = g_over[o];
            if (__float_as_int(ov.y) == row) {
                int s = __float_as_int(ov.x);
                float wt = ov.z;
                float4 v = ((const float4*)(x + (size_t)s * F))[lane];
                acc.x += wt * v.x;
                acc.y += wt * v.y;
                acc.z += wt * v.z;
                acc.w += wt * v.w;
            }
        }
    }

    float4 hv = ((const float4*)(h0 + (size_t)row * F))[lane];
    float4 S;
    S.x = oma * acc.x + alpha * hv.x;
    S.y = oma * acc.y + alpha * hv.y;
    S.z = oma * acc.z + alpha * hv.z;
    S.w = oma * acc.w + alpha * hv.w;
    ((float4*)(g_S + (size_t)row * F))[lane] = S;
}

// ---------------------------------------------------------------------------
// Kernel 4: HMMA epilogue.  out = S @ W' + x  via mma.sync m16n8k16 bf16
// with 2-term bf16 splitting (3 chains, fp32 accumulation):
//   D = Sa@Wa + Sb@Wa + Sa@Wb      (Sb@Wb ~ 1.6e-5 rel, dropped)
// smem: WT hi/lo = W'^T [n][k] bf16, row stride 134 u16 (268B: 4B-aligned,
// rows land on distinct banks); S tile hi/lo: 16 rows, same stride.
// Block = 256 thr / 8 warps; block-tile = 16 rows; each warp owns 2 n-tiles.
// Fragment loads are direct LDS.32 per the documented mma thread mapping:
//   A: a0=(m,k0) a1=(m+8,k0) a2=(m,k0+8) a3=(m+8,k0+8), m=lane/4, k0=(lane%4)*2
//   B: b0=(k0,n) b1=(k0+8,n), n=lane/4    D: c0/c1=(m,n0/n0+1), c2/c3=(m+8,..)
// ---------------------------------------------------------------------------
#define SPAD 134                       // u16 row stride (268 bytes)
#define OFF_WTA 0
#define OFF_WTB (128 * SPAD * 2)       // 34304
#define OFF_SA  (2 * 128 * SPAD * 2)   // 68608
#define OFF_SB  (OFF_SA + 16 * SPAD * 2)
#define SMEM_EPI (OFF_SB + 16 * SPAD * 2)   // 77184 bytes

#define MMA_BF16(c, a0, a1, a2, a3, b0, b1) \
    asm volatile("mma.sync.aligned.m16n8k16.row.col.f32.bf16.bf16.f32 " \
        "{%0,%1,%2,%3}, {%4,%5,%6,%7}, {%8,%9}, {%0,%1,%2,%3};" \
        : "+f"((c)[0]), "+f"((c)[1]), "+f"((c)[2]), "+f"((c)[3]) \
        : "r"(a0), "r"(a1), "r"(a2), "r"(a3), "r"(b0), "r"(b1))

__global__ void __launch_bounds__(256, 2)
mma_epilogue_kernel(const float* __restrict__ x,
                    const float* __restrict__ weight,
                    const float* __restrict__ lamda_p,
                    const int* __restrict__ l_p,
                    float* __restrict__ out,
                    int Nn) {
    extern __shared__ char sm[];
    u16* WTa = (u16*)(sm + OFF_WTA);
    u16* WTb = (u16*)(sm + OFF_WTB);
    u16* Sa  = (u16*)(sm + OFF_SA);
    u16* Sb  = (u16*)(sm + OFF_SB);

    int tid  = threadIdx.x;
    int lane = tid & 31;
    int wrp  = tid >> 5;

    float theta = logf(lamda_p[0] / (float)l_p[0] + 1.0f);
    float omt = 1.0f - theta;

    // Build WT hi/lo: WT[n][k] = W'[k][n] = theta*W[k][n] + (k==n)*(1-theta)
    for (int i = tid; i < F * F; i += 256) {
        int k = i >> 7;
        int n = i & 127;
        float v = theta * weight[i];
        if (k == n) v += omt;
        __nv_bfloat16 h = __float2bfloat16(v);
        float res = v - __bfloat162float(h);
        __nv_bfloat16 l = __float2bfloat16(res);
        WTa[n * SPAD + k] = *(u16*)&h;
        WTb[n * SPAD + k] = *(u16*)&l;
    }
    __syncthreads();

    int m0 = lane >> 2;                // fragment row within 16 (0..7)
    int cq = lane & 3;                 // k/n quad (0..3)
    int nt0 = wrp * 2;                 // this warp's two n-tiles

    int ntiles = (Nn + 15) >> 4;
    for (int t = blockIdx.x; t < ntiles; t += gridDim.x) {
        int row0 = t << 4;

        // ---- stage 16 S rows as bf16 hi+lo (coalesced read, convert once)
        for (int i = tid; i < 512; i += 256) {       // 512 float4 = 16x128 f32
            int r = i >> 5;
            int q = i & 31;
            int row = row0 + r;
            float4 v = (row < Nn)
                ? ((const float4*)(g_S + (size_t)row * F))[q]
                : make_float4(0.f, 0.f, 0.f, 0.f);
            __nv_bfloat162 h01 = __floats2bfloat162_rn(v.x, v.y);
            __nv_bfloat162 h23 = __floats2bfloat162_rn(v.z, v.w);
            __nv_bfloat162 l01 = __floats2bfloat162_rn(
                v.x - __bfloat162float(h01.x), v.y - __bfloat162float(h01.y));
            __nv_bfloat162 l23 = __floats2bfloat162_rn(
                v.z - __bfloat162float(h23.x), v.w - __bfloat162float(h23.y));
            int k = q * 4;
            *(u32*)&Sa[r * SPAD + k]     = *(u32*)&h01;
            *(u32*)&Sa[r * SPAD + k + 2] = *(u32*)&h23;
            *(u32*)&Sb[r * SPAD + k]     = *(u32*)&l01;
            *(u32*)&Sb[r * SPAD + k + 2] = *(u32*)&l23;
        }
        __syncthreads();

        // ---- mainloop: 8 k-steps x (2 n-tiles x 3 mma)
        float acc0[4] = {0.f, 0.f, 0.f, 0.f};
        float acc1[4] = {0.f, 0.f, 0.f, 0.f};

        #pragma unroll
        for (int ks = 0; ks < 8; ks++) {
            int kk = ks * 16 + cq * 2;
            u32 a0h = *(u32*)&Sa[m0 * SPAD + kk];
            u32 a1h = *(u32*)&Sa[(m0 + 8) * SPAD + kk];
            u32 a2h = *(u32*)&Sa[m0 * SPAD + kk + 8];
            u32 a3h = *(u32*)&Sa[(m0 + 8) * SPAD + kk + 8];
            u32 a0l = *(u32*)&Sb[m0 * SPAD + kk];
            u32 a1l = *(u32*)&Sb[(m0 + 8) * SPAD + kk];
            u32 a2l = *(u32*)&Sb[m0 * SPAD + kk + 8];
            u32 a3l = *(u32*)&Sb[(m0 + 8) * SPAD + kk + 8];

            {   // n-tile 0
                int n = nt0 * 8 + m0;
                u32 b0h = *(u32*)&WTa[n * SPAD + kk];
                u32 b1h = *(u32*)&WTa[n * SPAD + kk + 8];
                u32 b0l = *(u32*)&WTb[n * SPAD + kk];
                u32 b1l = *(u32*)&WTb[n * SPAD + kk + 8];
                MMA_BF16(acc0, a0h, a1h, a2h, a3h, b0h, b1h);
                MMA_BF16(acc0, a0l, a1l, a2l, a3l, b0h, b1h);
                MMA_BF16(acc0, a0h, a1h, a2h, a3h, b0l, b1l);
            }
            {   // n-tile 1
                int n = (nt0 + 1) * 8 + m0;
                u32 b0h = *(u32*)&WTa[n * SPAD + kk];
                u32 b1h = *(u32*)&WTa[n * SPAD + kk + 8];
                u32 b0l = *(u32*)&WTb[n * SPAD + kk];
                u32 b1l = *(u32*)&WTb[n * SPAD + kk + 8];
                MMA_BF16(acc1, a0h, a1h, a2h, a3h, b0h, b1h);
                MMA_BF16(acc1, a0l, a1l, a2l, a3l, b0h, b1h);
                MMA_BF16(acc1, a0h, a1h, a2h, a3h, b0l, b1l);
            }
        }

        // ---- writeout: D + x residual
        int r0 = row0 + m0;
        int r1 = row0 + m0 + 8;
        #pragma unroll
        for (int j = 0; j < 2; j++) {
            float* ac = j ? acc1 : acc0;
            int col = (nt0 + j) * 8 + cq * 2;
            if (r0 < Nn) {
                float2 xv = *(const float2*)&x[(size_t)r0 * F + col];
                float2 o = make_float2(ac[0] + xv.x, ac[1] + xv.y);
                *(float2*)&out[(size_t)r0 * F + col] = o;
            }
            if (r1 < Nn) {
                float2 xv = *(const float2*)&x[(size_t)r1 * F + col];
                float2 o = make_float2(ac[2] + xv.x, ac[3] + xv.y);
                *(float2*)&out[(size_t)r1 * F + col] = o;
            }
        }
        __syncthreads();   // protect S staging before next tile
    }
}

// ---------------------------------------------------------------------------
extern "C" void kernel_launch(void* const* d_in, const int* in_sizes, int n_in,
                              void* d_out, int out_size) {
    const float* x      = (const float*)d_in[0];
    const float* h0     = (const float*)d_in[1];
    const float* ew     = (const float*)d_in[2];
    const float* weight = (const float*)d_in[3];
    const float* lamda  = (const float*)d_in[4];
    const float* alpha  = (const float*)d_in[5];
    const int*   esrc   = (const int*)d_in[6];
    const int*   edst   = (const int*)d_in[7];
    const int*   lp     = (const int*)d_in[8];

    int Nn = in_sizes[0] / F;
    int E  = in_sizes[2];
    float* out = (float*)d_out;

    zero_cnt_kernel<<<(Nn + 255) / 256, 256>>>(Nn);
    fill_kernel<<<(E + 255) / 256, 256>>>(ew, esrc, edst, E);

    long long gthreads = (long long)Nn * 32;
    gather_kernel<<<(int)((gthreads + 255) / 256), 256>>>(x, h0, alpha, Nn);

    cudaFuncSetAttribute(mma_epilogue_kernel,
                         cudaFuncAttributeMaxDynamicSharedMemorySize, SMEM_EPI);
    mma_epilogue_kernel<<<296, 256, SMEM_EPI>>>(x, weight, lamda, lp, out, Nn);
}

// round 11
// speedup vs baseline: 1.5108x; 1.2077x over previous
#include <cuda_runtime.h>
#include <cuda_bf16.h>
#include <math.h>

#define F 128
#define NMAX 50000
#define EMAX 800000
#define CAP 64      // bucket capacity per destination row (P(deg>=64) ~ 1e-13)

typedef unsigned int   u32;
typedef unsigned short u16;

// static scratch (no allocations allowed)
__device__ float  g_S[(size_t)NMAX * F];           // S = (1-a)*A@x + a*h0
__device__ float2 g_slots[(size_t)NMAX * CAP];     // (src_bits, w) buckets
__device__ int    g_cnt[NMAX];
__device__ float4 g_over[EMAX];                    // overflow edges
__device__ int    g_overcnt;

// ---------------------------------------------------------------------------
// Kernel 1: zero bucket counters + overflow counter
// ---------------------------------------------------------------------------
__global__ void zero_cnt_kernel(int Nn) {
    int i = blockIdx.x * blockDim.x + threadIdx.x;
    if (i < Nn) g_cnt[i] = 0;
    if (i == 0) g_overcnt = 0;
}

// ---------------------------------------------------------------------------
// Kernel 2: bucket fill. One thread per edge (R3/R8-proven).
// ---------------------------------------------------------------------------
__global__ void fill_kernel(const float* __restrict__ edge_w,
                            const int* __restrict__ edge_src,
                            const int* __restrict__ edge_dst,
                            int E) {
    int e = blockIdx.x * blockDim.x + threadIdx.x;
    if (e >= E) return;
    int d = edge_dst[e];
    int s = edge_src[e];
    float w = edge_w[e];
    int pos = atomicAdd(&g_cnt[d], 1);
    if (pos < CAP) {
        g_slots[(size_t)d * CAP + pos] = make_float2(__int_as_float(s), w);
    } else {
        int o = atomicAdd(&g_overcnt, 1);
        if (o < EMAX)
            g_over[o] = make_float4(__int_as_float(s), __int_as_float(d), w, 0.f);
    }
}

// ---------------------------------------------------------------------------
// Kernel 3: gather + S fuse. One warp per row (R8-proven, inline overflow).
// ---------------------------------------------------------------------------
__global__ void gather_kernel(const float* __restrict__ x,
                              const float* __restrict__ h0,
                              const float* __restrict__ alpha_p,
                              int Nn) {
    int gtid = blockIdx.x * blockDim.x + threadIdx.x;
    int row = gtid >> 5;
    int lane = gtid & 31;
    if (row >= Nn) return;

    float alpha = alpha_p[0];
    float oma = 1.0f - alpha;

    int cnt_raw = g_cnt[row];
    int cnt = min(cnt_raw, CAP);

    float4 acc = make_float4(0.f, 0.f, 0.f, 0.f);
    const float2* slotp = g_slots + (size_t)row * CAP;

    for (int base = 0; base < cnt; base += 32) {
        int m = min(32, cnt - base);
        float2 myslot = (lane < m) ? slotp[base + lane] : make_float2(0.f, 0.f);
        int ms = __float_as_int(myslot.x);
        #pragma unroll 4
        for (int e = 0; e < m; e++) {
            int   s  = __shfl_sync(0xffffffffu, ms, e);
            float wt = __shfl_sync(0xffffffffu, myslot.y, e);
            float4 v = ((const float4*)(x + (size_t)s * F))[lane];
            acc.x += wt * v.x;
            acc.y += wt * v.y;
            acc.z += wt * v.z;
            acc.w += wt * v.w;
        }
    }

    if (cnt_raw > CAP) {                       // statistically never
        int oc = g_overcnt;
        if (oc > EMAX) oc = EMAX;
        for (int o = 0; o < oc; o++) {
            float4 ov = g_over[o];
            if (__float_as_int(ov.y) == row) {
                int s = __float_as_int(ov.x);
                float wt = ov.z;
                float4 v = ((const float4*)(x + (size_t)s * F))[lane];
                acc.x += wt * v.x;
                acc.y += wt * v.y;
                acc.z += wt * v.z;
                acc.w += wt * v.w;
            }
        }
    }

    float4 hv = ((const float4*)(h0 + (size_t)row * F))[lane];
    float4 S;
    S.x = oma * acc.x + alpha * hv.x;
    S.y = oma * acc.y + alpha * hv.y;
    S.z = oma * acc.z + alpha * hv.z;
    S.w = oma * acc.w + alpha * hv.w;
    ((float4*)(g_S + (size_t)row * F))[lane] = S;
}

// ---------------------------------------------------------------------------
// Kernel 4: HMMA epilogue.  out = S @ W' + x  via mma.sync m16n8k16 bf16,
// 2-term bf16 split: D = Sa@Wa + Sb@Wa + Sa@Wb  (fp32 accum).
// R11 changes vs R10 (which passed at 52.6us, L1-bound 58.7%):
//   - B fragments (W' fixed) hoisted into registers BEFORE the tile loop:
//     zero in-loop B LDS traffic.
//   - A fragments via ldmatrix.x4 (2 per k-step instead of 8 LDS.32).
//   - SPAD 134 -> 136 u16 (272B rows, 16B-aligned for ldmatrix; rows hit
//     banks 0,4,..,28 -> phase-distinct).
// ---------------------------------------------------------------------------
#define SPAD 136                        // u16 row stride (272 bytes)
#define OFF_WTA 0
#define OFF_WTB (128 * SPAD * 2)        // 34816
#define OFF_SA  (2 * 128 * SPAD * 2)    // 69632
#define OFF_SB  (OFF_SA + 16 * SPAD * 2)
#define SMEM_EPI (OFF_SB + 16 * SPAD * 2)   // 78336 bytes

#define MMA_BF16(c, a0, a1, a2, a3, b0, b1) \
    asm volatile("mma.sync.aligned.m16n8k16.row.col.f32.bf16.bf16.f32 " \
        "{%0,%1,%2,%3}, {%4,%5,%6,%7}, {%8,%9}, {%0,%1,%2,%3};" \
        : "+f"((c)[0]), "+f"((c)[1]), "+f"((c)[2]), "+f"((c)[3]) \
        : "r"(a0), "r"(a1), "r"(a2), "r"(a3), "r"(b0), "r"(b1))

#define LDMATRIX_X4(r0, r1, r2, r3, addr) \
    asm volatile("ldmatrix.sync.aligned.m8n8.x4.shared.b16 {%0,%1,%2,%3}, [%4];" \
        : "=r"(r0), "=r"(r1), "=r"(r2), "=r"(r3) : "r"(addr))

__device__ __forceinline__ u32 smem_u32(const void* p) {
    u32 a;
    asm("{ .reg .u64 t; cvta.to.shared.u64 t, %1; cvt.u32.u64 %0, t; }"
        : "=r"(a) : "l"(p));
    return a;
}

__global__ void __launch_bounds__(256, 2)
mma_epilogue_kernel(const float* __restrict__ x,
                    const float* __restrict__ weight,
                    const float* __restrict__ lamda_p,
                    const int* __restrict__ l_p,
                    float* __restrict__ out,
                    int Nn) {
    extern __shared__ char sm[];
    u16* WTa = (u16*)(sm + OFF_WTA);
    u16* WTb = (u16*)(sm + OFF_WTB);
    u16* Sa  = (u16*)(sm + OFF_SA);
    u16* Sb  = (u16*)(sm + OFF_SB);

    int tid  = threadIdx.x;
    int lane = tid & 31;
    int wrp  = tid >> 5;

    float theta = logf(lamda_p[0] / (float)l_p[0] + 1.0f);
    float omt = 1.0f - theta;

    // Build WT hi/lo: WT[n][k] = W'[k][n] = theta*W[k][n] + (k==n)*(1-theta)
    for (int i = tid; i < F * F; i += 256) {
        int k = i >> 7;
        int n = i & 127;
        float v = theta * weight[i];
        if (k == n) v += omt;
        __nv_bfloat16 h = __float2bfloat16(v);
        float res = v - __bfloat162float(h);
        __nv_bfloat16 l = __float2bfloat16(res);
        WTa[n * SPAD + k] = *(u16*)&h;
        WTb[n * SPAD + k] = *(u16*)&l;
    }
    __syncthreads();

    int m0 = lane >> 2;                // fragment row within 8 (0..7)
    int cq = lane & 3;                 // k/n quad (0..3)
    int nt0 = wrp * 2;                 // this warp's two n-tiles

    // ---- hoist B fragments (W' constant across all tiles): 64 u32 regs
    u32 Bf[2][8][4];                   // [n-tile][k-step][b0h,b1h,b0l,b1l]
    #pragma unroll
    for (int j = 0; j < 2; j++) {
        int n = (nt0 + j) * 8 + m0;
        #pragma unroll
        for (int ks = 0; ks < 8; ks++) {
            int kk = ks * 16 + cq * 2;
            Bf[j][ks][0] = *(u32*)&WTa[n * SPAD + kk];
            Bf[j][ks][1] = *(u32*)&WTa[n * SPAD + kk + 8];
            Bf[j][ks][2] = *(u32*)&WTb[n * SPAD + kk];
            Bf[j][ks][3] = *(u32*)&WTb[n * SPAD + kk + 8];
        }
    }

    // ldmatrix lane addressing: row = lane&15, col-block = (lane>>4)*8
    u32 lm_row = lane & 15;
    u32 lm_col = (lane >> 4) << 3;
    u32 addrSa = smem_u32(Sa) + (lm_row * SPAD + lm_col) * 2;
    u32 addrSb = smem_u32(Sb) + (lm_row * SPAD + lm_col) * 2;

    int ntiles = (Nn + 15) >> 4;
    for (int t = blockIdx.x; t < ntiles; t += gridDim.x) {
        int row0 = t << 4;

        // ---- stage 16 S rows as bf16 hi+lo (coalesced read, convert once)
        for (int i = tid; i < 512; i += 256) {       // 512 float4 = 16x128 f32
            int r = i >> 5;
            int q = i & 31;
            int row = row0 + r;
            float4 v = (row < Nn)
                ? ((const float4*)(g_S + (size_t)row * F))[q]
                : make_float4(0.f, 0.f, 0.f, 0.f);
            __nv_bfloat162 h01 = __floats2bfloat162_rn(v.x, v.y);
            __nv_bfloat162 h23 = __floats2bfloat162_rn(v.z, v.w);
            __nv_bfloat162 l01 = __floats2bfloat162_rn(
                v.x - __bfloat162float(h01.x), v.y - __bfloat162float(h01.y));
            __nv_bfloat162 l23 = __floats2bfloat162_rn(
                v.z - __bfloat162float(h23.x), v.w - __bfloat162float(h23.y));
            int k = q * 4;
            *(u32*)&Sa[r * SPAD + k]     = *(u32*)&h01;
            *(u32*)&Sa[r * SPAD + k + 2] = *(u32*)&h23;
            *(u32*)&Sb[r * SPAD + k]     = *(u32*)&l01;
            *(u32*)&Sb[r * SPAD + k + 2] = *(u32*)&l23;
        }
        __syncthreads();

        // ---- mainloop: 8 k-steps x (ldmatrix A hi/lo + 6 mma)
        float acc0[4] = {0.f, 0.f, 0.f, 0.f};
        float acc1[4] = {0.f, 0.f, 0.f, 0.f};

        #pragma unroll
        for (int ks = 0; ks < 8; ks++) {
            u32 ah0, ah1, ah2, ah3, al0, al1, al2, al3;
            LDMATRIX_X4(ah0, ah1, ah2, ah3, addrSa + ks * 32);
            LDMATRIX_X4(al0, al1, al2, al3, addrSb + ks * 32);

            MMA_BF16(acc0, ah0, ah1, ah2, ah3, Bf[0][ks][0], Bf[0][ks][1]);
            MMA_BF16(acc0, al0, al1, al2, al3, Bf[0][ks][0], Bf[0][ks][1]);
            MMA_BF16(acc0, ah0, ah1, ah2, ah3, Bf[0][ks][2], Bf[0][ks][3]);

            MMA_BF16(acc1, ah0, ah1, ah2, ah3, Bf[1][ks][0], Bf[1][ks][1]);
            MMA_BF16(acc1, al0, al1, al2, al3, Bf[1][ks][0], Bf[1][ks][1]);
            MMA_BF16(acc1, ah0, ah1, ah2, ah3, Bf[1][ks][2], Bf[1][ks][3]);
        }

        // ---- writeout: D + x residual
        int r0 = row0 + m0;
        int r1 = row0 + m0 + 8;
        #pragma unroll
        for (int j = 0; j < 2; j++) {
            float* ac = j ? acc1 : acc0;
            int col = (nt0 + j) * 8 + cq * 2;
            if (r0 < Nn) {
                float2 xv = *(const float2*)&x[(size_t)r0 * F + col];
                float2 o = make_float2(ac[0] + xv.x, ac[1] + xv.y);
                *(float2*)&out[(size_t)r0 * F + col] = o;
            }
            if (r1 < Nn) {
                float2 xv = *(const float2*)&x[(size_t)r1 * F + col];
                float2 o = make_float2(ac[2] + xv.x, ac[3] + xv.y);
                *(float2*)&out[(size_t)r1 * F + col] = o;
            }
        }
        __syncthreads();   // protect S staging before next tile
    }
}

// ---------------------------------------------------------------------------
extern "C" void kernel_launch(void* const* d_in, const int* in_sizes, int n_in,
                              void* d_out, int out_size) {
    const float* x      = (const float*)d_in[0];
    const float* h0     = (const float*)d_in[1];
    const float* ew     = (const float*)d_in[2];
    const float* weight = (const float*)d_in[3];
    const float* lamda  = (const float*)d_in[4];
    const float* alpha  = (const float*)d_in[5];
    const int*   esrc   = (const int*)d_in[6];
    const int*   edst   = (const int*)d_in[7];
    const int*   lp     = (const int*)d_in[8];

    int Nn = in_sizes[0] / F;
    int E  = in_sizes[2];
    float* out = (float*)d_out;

    zero_cnt_kernel<<<(Nn + 255) / 256, 256>>>(Nn);
    fill_kernel<<<(E + 255) / 256, 256>>>(ew, esrc, edst, E);

    long long gthreads = (long long)Nn * 32;
    gather_kernel<<<(int)((gthreads + 255) / 256), 256>>>(x, h0, alpha, Nn);

    cudaFuncSetAttribute(mma_epilogue_kernel,
                         cudaFuncAttributeMaxDynamicSharedMemorySize, SMEM_EPI);
    mma_epilogue_kernel<<<296, 256, SMEM_EPI>>>(x, weight, lamda, lp, out, Nn);
}

// round 12
// speedup vs baseline: 1.5535x; 1.0282x over previous
#include <cuda_runtime.h>
#include <cuda_bf16.h>
#include <math.h>

#define F 128
#define NMAX 50000
#define EMAX 800000
#define CAP 64      // bucket capacity per destination row (P(deg>=64) ~ 1e-13)

typedef unsigned int       u32;
typedef unsigned short     u16;
typedef unsigned long long u64;

// static scratch (no allocations allowed; zero-initialized at load)
__device__ u16    g_Shi[(size_t)NMAX * F];         // bf16 hi of S
__device__ u16    g_Slo[(size_t)NMAX * F];         // bf16 residual of S
__device__ float2 g_slots[(size_t)NMAX * CAP];     // (src_bits, w) buckets
__device__ int    g_cnt[NMAX];                     // reset by epilogue for next call
__device__ float4 g_over[EMAX];                    // overflow edges
__device__ int    g_overcnt;

// ---------------------------------------------------------------------------
// Kernel 1: bucket fill. One thread per edge (R3/R8-proven).
// g_cnt arrives zeroed: static init on call 1, epilogue-reset on later calls.
// ---------------------------------------------------------------------------
__global__ void fill_kernel(const float* __restrict__ edge_w,
                            const int* __restrict__ edge_src,
                            const int* __restrict__ edge_dst,
                            int E) {
    int e = blockIdx.x * blockDim.x + threadIdx.x;
    if (e >= E) return;
    int d = edge_dst[e];
    int s = edge_src[e];
    float w = edge_w[e];
    int pos = atomicAdd(&g_cnt[d], 1);
    if (pos < CAP) {
        g_slots[(size_t)d * CAP + pos] = make_float2(__int_as_float(s), w);
    } else {
        int o = atomicAdd(&g_overcnt, 1);
        if (o < EMAX)
            g_over[o] = make_float4(__int_as_float(s), __int_as_float(d), w, 0.f);
    }
}

// ---------------------------------------------------------------------------
// Kernel 2: gather + S fuse + bf16 hi/lo split. One warp per row.
//   S[row] = (1-alpha)*sum_e w_e*x[src_e] + alpha*h0[row]
// writes g_Shi/g_Slo (bf16 value + bf16 residual; fp32 math up to here).
// ---------------------------------------------------------------------------
__global__ void gather_kernel(const float* __restrict__ x,
                              const float* __restrict__ h0,
                              const float* __restrict__ alpha_p,
                              int Nn) {
    int gtid = blockIdx.x * blockDim.x + threadIdx.x;
    int row = gtid >> 5;
    int lane = gtid & 31;
    if (row >= Nn) return;

    float alpha = alpha_p[0];
    float oma = 1.0f - alpha;

    int cnt_raw = g_cnt[row];
    int cnt = min(cnt_raw, CAP);

    float4 acc = make_float4(0.f, 0.f, 0.f, 0.f);
    const float2* slotp = g_slots + (size_t)row * CAP;

    for (int base = 0; base < cnt; base += 32) {
        int m = min(32, cnt - base);
        float2 myslot = (lane < m) ? slotp[base + lane] : make_float2(0.f, 0.f);
        int ms = __float_as_int(myslot.x);
        #pragma unroll 4
        for (int e = 0; e < m; e++) {
            int   s  = __shfl_sync(0xffffffffu, ms, e);
            float wt = __shfl_sync(0xffffffffu, myslot.y, e);
            float4 v = ((const float4*)(x + (size_t)s * F))[lane];
            acc.x += wt * v.x;
            acc.y += wt * v.y;
            acc.z += wt * v.z;
            acc.w += wt * v.w;
        }
    }

    if (cnt_raw > CAP) {                       // statistically never
        int oc = g_overcnt;
        if (oc > EMAX) oc = EMAX;
        for (int o = 0; o < oc; o++) {
            float4 ov = g_over[o];
            if (__float_as_int(ov.y) == row) {
                int s = __float_as_int(ov.x);
                float wt = ov.z;
                float4 v = ((const float4*)(x + (size_t)s * F))[lane];
                acc.x += wt * v.x;
                acc.y += wt * v.y;
                acc.z += wt * v.z;
                acc.w += wt * v.w;
            }
        }
    }

    float4 hv = ((const float4*)(h0 + (size_t)row * F))[lane];
    float Sx = oma * acc.x + alpha * hv.x;
    float Sy = oma * acc.y + alpha * hv.y;
    float Sz = oma * acc.z + alpha * hv.z;
    float Sw = oma * acc.w + alpha * hv.w;

    // bf16 split (value + residual), 4 cols per lane, one u64 store each
    __nv_bfloat162 h01 = __floats2bfloat162_rn(Sx, Sy);
    __nv_bfloat162 h23 = __floats2bfloat162_rn(Sz, Sw);
    __nv_bfloat162 l01 = __floats2bfloat162_rn(
        Sx - __bfloat162float(h01.x), Sy - __bfloat162float(h01.y));
    __nv_bfloat162 l23 = __floats2bfloat162_rn(
        Sz - __bfloat162float(h23.x), Sw - __bfloat162float(h23.y));
    u64 hvv = (u64)(*(u32*)&h01) | ((u64)(*(u32*)&h23) << 32);
    u64 lvv = (u64)(*(u32*)&l01) | ((u64)(*(u32*)&l23) << 32);
    *(u64*)&g_Shi[(size_t)row * F + 4 * lane] = hvv;
    *(u64*)&g_Slo[(size_t)row * F + 4 * lane] = lvv;
}

// ---------------------------------------------------------------------------
// Kernel 3: HMMA epilogue.  out = S @ W' + x  via mma.sync m16n8k16 bf16,
// 2-term split: D = Sa@Wa + Sb@Wa + Sa@Wb  (fp32 accum).
// R12 vs R11 (36.9us): staging is pure LDG.128->STS.128 (split moved to
// gather); also resets g_cnt/g_overcnt for the next invocation (zero_cnt
// kernel deleted).
// ---------------------------------------------------------------------------
#define SPAD 136                        // u16 row stride (272 bytes)
#define OFF_WTA 0
#define OFF_WTB (128 * SPAD * 2)        // 34816
#define OFF_SA  (2 * 128 * SPAD * 2)    // 69632
#define OFF_SB  (OFF_SA + 16 * SPAD * 2)
#define SMEM_EPI (OFF_SB + 16 * SPAD * 2)   // 78336 bytes

#define MMA_BF16(c, a0, a1, a2, a3, b0, b1) \
    asm volatile("mma.sync.aligned.m16n8k16.row.col.f32.bf16.bf16.f32 " \
        "{%0,%1,%2,%3}, {%4,%5,%6,%7}, {%8,%9}, {%0,%1,%2,%3};" \
        : "+f"((c)[0]), "+f"((c)[1]), "+f"((c)[2]), "+f"((c)[3]) \
        : "r"(a0), "r"(a1), "r"(a2), "r"(a3), "r"(b0), "r"(b1))

#define LDMATRIX_X4(r0, r1, r2, r3, addr) \
    asm volatile("ldmatrix.sync.aligned.m8n8.x4.shared.b16 {%0,%1,%2,%3}, [%4];" \
        : "=r"(r0), "=r"(r1), "=r"(r2), "=r"(r3) : "r"(addr))

__device__ __forceinline__ u32 smem_u32(const void* p) {
    u32 a;
    asm("{ .reg .u64 t; cvta.to.shared.u64 t, %1; cvt.u32.u64 %0, t; }"
        : "=r"(a) : "l"(p));
    return a;
}

__global__ void __launch_bounds__(256, 2)
mma_epilogue_kernel(const float* __restrict__ x,
                    const float* __restrict__ weight,
                    const float* __restrict__ lamda_p,
                    const int* __restrict__ l_p,
                    float* __restrict__ out,
                    int Nn) {
    extern __shared__ char sm[];
    u16* WTa = (u16*)(sm + OFF_WTA);
    u16* WTb = (u16*)(sm + OFF_WTB);
    u16* Sa  = (u16*)(sm + OFF_SA);
    u16* Sb  = (u16*)(sm + OFF_SB);

    int tid  = threadIdx.x;
    int lane = tid & 31;
    int wrp  = tid >> 5;

    // reset counters for the NEXT invocation (off the critical path;
    // fill/gather of this call already consumed them)
    {
        int gid = blockIdx.x * blockDim.x + tid;
        if (gid < Nn) g_cnt[gid] = 0;
        if (gid == 0) g_overcnt = 0;
    }

    float theta = logf(lamda_p[0] / (float)l_p[0] + 1.0f);
    float omt = 1.0f - theta;

    // Build WT hi/lo: WT[n][k] = W'[k][n] = theta*W[k][n] + (k==n)*(1-theta)
    for (int i = tid; i < F * F; i += 256) {
        int k = i >> 7;
        int n = i & 127;
        float v = theta * weight[i];
        if (k == n) v += omt;
        __nv_bfloat16 h = __float2bfloat16(v);
        float res = v - __bfloat162float(h);
        __nv_bfloat16 l = __float2bfloat16(res);
        WTa[n * SPAD + k] = *(u16*)&h;
        WTb[n * SPAD + k] = *(u16*)&l;
    }
    __syncthreads();

    int m0 = lane >> 2;                // fragment row (0..7)
    int cq = lane & 3;                 // k/n quad (0..3)
    int nt0 = wrp * 2;                 // this warp's two n-tiles

    // ---- hoist B fragments (W' constant across all tiles): 64 u32 regs
    u32 Bf[2][8][4];                   // [n-tile][k-step][b0h,b1h,b0l,b1l]
    #pragma unroll
    for (int j = 0; j < 2; j++) {
        int n = (nt0 + j) * 8 + m0;
        #pragma unroll
        for (int ks = 0; ks < 8; ks++) {
            int kk = ks * 16 + cq * 2;
            Bf[j][ks][0] = *(u32*)&WTa[n * SPAD + kk];
            Bf[j][ks][1] = *(u32*)&WTa[n * SPAD + kk + 8];
            Bf[j][ks][2] = *(u32*)&WTb[n * SPAD + kk];
            Bf[j][ks][3] = *(u32*)&WTb[n * SPAD + kk + 8];
        }
    }

    // ldmatrix lane addressing: row = lane&15, col-block = (lane>>4)*8
    u32 lm_row = lane & 15;
    u32 lm_col = (lane >> 4) << 3;
    u32 addrSa = smem_u32(Sa) + (lm_row * SPAD + lm_col) * 2;
    u32 addrSb = smem_u32(Sb) + (lm_row * SPAD + lm_col) * 2;

    int ntiles = (Nn + 15) >> 4;
    for (int t = blockIdx.x; t < ntiles; t += gridDim.x) {
        int row0 = t << 4;

        // ---- stage 16 S rows: pure LDG.128 -> STS.128 copy (hi and lo).
        // thread i: r = i>>4 (row), seg = i&15 (8-col segment)
        {
            int r = tid >> 4;
            int seg = tid & 15;
            int row = row0 + r;
            size_t gidx = (size_t)row * F + seg * 8;
            uint4 hv = (row < Nn) ? *(const uint4*)&g_Shi[gidx]
                                  : make_uint4(0, 0, 0, 0);
            uint4 lv = (row < Nn) ? *(const uint4*)&g_Slo[gidx]
                                  : make_uint4(0, 0, 0, 0);
            *(uint4*)&Sa[r * SPAD + seg * 8] = hv;
            *(uint4*)&Sb[r * SPAD + seg * 8] = lv;
        }
        __syncthreads();

        // ---- mainloop: 8 k-steps x (ldmatrix A hi/lo + 6 mma)
        float acc0[4] = {0.f, 0.f, 0.f, 0.f};
        float acc1[4] = {0.f, 0.f, 0.f, 0.f};

        #pragma unroll
        for (int ks = 0; ks < 8; ks++) {
            u32 ah0, ah1, ah2, ah3, al0, al1, al2, al3;
            LDMATRIX_X4(ah0, ah1, ah2, ah3, addrSa + ks * 32);
            LDMATRIX_X4(al0, al1, al2, al3, addrSb + ks * 32);

            MMA_BF16(acc0, ah0, ah1, ah2, ah3, Bf[0][ks][0], Bf[0][ks][1]);
            MMA_BF16(acc0, al0, al1, al2, al3, Bf[0][ks][0], Bf[0][ks][1]);
            MMA_BF16(acc0, ah0, ah1, ah2, ah3, Bf[0][ks][2], Bf[0][ks][3]);

            MMA_BF16(acc1, ah0, ah1, ah2, ah3, Bf[1][ks][0], Bf[1][ks][1]);
            MMA_BF16(acc1, al0, al1, al2, al3, Bf[1][ks][0], Bf[1][ks][1]);
            MMA_BF16(acc1, ah0, ah1, ah2, ah3, Bf[1][ks][2], Bf[1][ks][3]);
        }

        // ---- writeout: D + x residual
        int r0 = row0 + m0;
        int r1 = row0 + m0 + 8;
        #pragma unroll
        for (int j = 0; j < 2; j++) {
            float* ac = j ? acc1 : acc0;
            int col = (nt0 + j) * 8 + cq * 2;
            if (r0 < Nn) {
                float2 xv = *(const float2*)&x[(size_t)r0 * F + col];
                float2 o = make_float2(ac[0] + xv.x, ac[1] + xv.y);
                *(float2*)&out[(size_t)r0 * F + col] = o;
            }
            if (r1 < Nn) {
                float2 xv = *(const float2*)&x[(size_t)r1 * F + col];
                float2 o = make_float2(ac[2] + xv.x, ac[3] + xv.y);
                *(float2*)&out[(size_t)r1 * F + col] = o;
            }
        }
        __syncthreads();   // protect S staging before next tile
    }
}

// ---------------------------------------------------------------------------
extern "C" void kernel_launch(void* const* d_in, const int* in_sizes, int n_in,
                              void* d_out, int out_size) {
    const float* x      = (const float*)d_in[0];
    const float* h0     = (const float*)d_in[1];
    const float* ew     = (const float*)d_in[2];
    const float* weight = (const float*)d_in[3];
    const float* lamda  = (const float*)d_in[4];
    const float* alpha  = (const float*)d_in[5];
    const int*   esrc   = (const int*)d_in[6];
    const int*   edst   = (const int*)d_in[7];
    const int*   lp     = (const int*)d_in[8];

    int Nn = in_sizes[0] / F;
    int E  = in_sizes[2];
    float* out = (float*)d_out;

    // 1) bucket fill (counters zeroed by static init / prior epilogue)
    fill_kernel<<<(E + 255) / 256, 256>>>(ew, esrc, edst, E);

    // 2) gather + S fuse + bf16 split (one warp per row)
    long long gthreads = (long long)Nn * 32;
    gather_kernel<<<(int)((gthreads + 255) / 256), 256>>>(x, h0, alpha, Nn);

    // 3) HMMA epilogue (+ counter reset for next call)
    cudaFuncSetAttribute(mma_epilogue_kernel,
                         cudaFuncAttributeMaxDynamicSharedMemorySize, SMEM_EPI);
    mma_epilogue_kernel<<<296, 256, SMEM_EPI>>>(x, weight, lamda, lp, out, Nn);
}